// round 9
// baseline (speedup 1.0000x reference)
#include <cuda_runtime.h>
#include <cuda_bf16.h>
#include <math.h>

// Problem constants (shapes fixed by the dataset)
#define NMAX  100000
#define EMAX  1600000
#define F1    128
#define F2    64
#define SCAN_B 512
#define NBMAX ((NMAX + SCAN_B - 1) / SCAN_B)   // 196

// ---------------- scratch (static device globals; no allocation allowed) ----
__device__ int    g_is64;                 // 1 if edge_index is int64, else int32
__device__ int    g_cnt[NMAX];
__device__ int    g_bsum[NBMAX];
__device__ int    g_boff[NBMAX];
__device__ int    g_rowstart[NMAX + 1];
__device__ int    g_cursor[NMAX];
__device__ float  g_dinv[NMAX];
__device__ int    g_rows[EMAX];
__device__ int    g_cols[EMAX];
__device__ int    g_csr[EMAX];
__device__ float4 g_h1s[(size_t)NMAX * F1 / 4];     // (x @ W1) * dinv[row]
__device__ float4 g_hidden[(size_t)NMAX * F1 / 4];  // relu(dinv*(sum)+b1)
__device__ float4 g_h2s[(size_t)NMAX * F2 / 4];     // (hidden @ W2) * dinv[row]

// ---------------- packed f32x2 helpers --------------------------------------

__device__ __forceinline__ void ffma2(unsigned long long& d,
                                      unsigned long long a,
                                      unsigned long long b) {
    asm("fma.rn.f32x2 %0, %1, %2, %0;" : "+l"(d) : "l"(a), "l"(b));
}
__device__ __forceinline__ unsigned long long bcast2(float x) {
    unsigned long long r;
    asm("mov.b64 %0, {%1, %1};" : "=l"(r) : "f"(x));
    return r;
}
__device__ __forceinline__ float2 unpack2(unsigned long long v) {
    float2 r;
    asm("mov.b64 {%0, %1}, %2;" : "=f"(r.x), "=f"(r.y) : "l"(v));
    return r;
}

// ---------------- build kernels ---------------------------------------------

// Probe dtype of edge_index: int64 values < 2^31 have zero high words.
__global__ void k_detect(const int* __restrict__ ei_raw) {
    if (threadIdx.x == 0 && blockIdx.x == 0) {
        int any = 0;
        for (int i = 0; i < 64; i++) any |= ei_raw[2 * i + 1];
        g_is64 = (any == 0) ? 1 : 0;
    }
}

__global__ void k_zero_cnt(int N) {
    int i = blockIdx.x * blockDim.x + threadIdx.x;
    if (i < N) g_cnt[i] = 0;
}

// Decode edge indices (int32 or int64 per flag), validate, count in-degree.
__global__ void k_count(const void* __restrict__ ei_raw, int E, int N) {
    int e = blockIdx.x * blockDim.x + threadIdx.x;
    if (e >= E) return;
    int r, c;
    if (g_is64) {
        const long long* ei = (const long long*)ei_raw;
        r = (int)ei[e];
        c = (int)ei[(size_t)E + e];
    } else {
        const int* ei = (const int*)ei_raw;
        r = ei[e];
        c = ei[(size_t)E + e];
    }
    if ((unsigned)r >= (unsigned)N || (unsigned)c >= (unsigned)N) {
        g_rows[e] = -1; g_cols[e] = -1;
        return;
    }
    g_rows[e] = r;
    g_cols[e] = c;
    atomicAdd(&g_cnt[c], 1);
}

// Phase 1: per-block sums of counts.
__global__ void __launch_bounds__(SCAN_B) k_scan_partial(int N) {
    __shared__ int red[SCAN_B / 32];
    int b = blockIdx.x, tid = threadIdx.x;
    int i = b * SCAN_B + tid;
    int v = (i < N) ? g_cnt[i] : 0;
    for (int o = 16; o > 0; o >>= 1) v += __shfl_down_sync(0xffffffffu, v, o);
    if ((tid & 31) == 0) red[tid >> 5] = v;
    __syncthreads();
    if (tid < SCAN_B / 32) {
        int s = red[tid];
        for (int o = (SCAN_B / 64); o > 0; o >>= 1) s += __shfl_down_sync(0xffffu, s, o);
        if (tid == 0) g_bsum[b] = s;
    }
}

// Phase 2: single block scans block sums -> exclusive offsets; writes total.
__global__ void __launch_bounds__(256) k_scan_blk(int nb, int N) {
    __shared__ int sh[256];
    int tid = threadIdx.x;
    int v = (tid < nb) ? g_bsum[tid] : 0;
    sh[tid] = v;
    __syncthreads();
    for (int o = 1; o < 256; o <<= 1) {
        int t = (tid >= o) ? sh[tid - o] : 0;
        __syncthreads();
        sh[tid] += t;
        __syncthreads();
    }
    if (tid < nb) g_boff[tid] = sh[tid] - v;       // exclusive
    if (tid == 255) g_rowstart[N] = sh[255];       // total
}

// Phase 3: block-local exclusive scan + offset -> rowstart/cursor/dinv.
__global__ void __launch_bounds__(SCAN_B) k_scan_apply(int N) {
    __shared__ int sh[SCAN_B];
    int b = blockIdx.x, tid = threadIdx.x;
    int i = b * SCAN_B + tid;
    int v = (i < N) ? g_cnt[i] : 0;
    sh[tid] = v;
    __syncthreads();
    for (int o = 1; o < SCAN_B; o <<= 1) {
        int t = (tid >= o) ? sh[tid - o] : 0;
        __syncthreads();
        sh[tid] += t;
        __syncthreads();
    }
    if (i < N) {
        int base = g_boff[b] + sh[tid] - v;        // exclusive prefix
        g_rowstart[i] = base;
        g_cursor[i]   = base;
        g_dinv[i] = rsqrtf((float)(v + 1));        // +1 self loop
    }
}

// Fill CSR: for each valid edge, place its source row into target's bucket.
__global__ void k_fill(int E) {
    int e = blockIdx.x * blockDim.x + threadIdx.x;
    if (e < E) {
        int c = g_cols[e];
        if (c < 0) return;
        int pos = atomicAdd(&g_cursor[c], 1);
        g_csr[pos] = g_rows[e];
    }
}

// ---------------- compute kernels -------------------------------------------

// Register-tiled GEMM1 with packed f32x2 FMA.
// Block tile: 32 nodes x 64 features (half of F1, chosen by blockIdx.y).
// 256 threads, each computes 2 nodes x 4 features via 4 FFMA2/k.
__global__ void __launch_bounds__(256) k_gemm1(const float* __restrict__ x,
                                               const float* __restrict__ W1, int N) {
    __shared__ float4 W4s[F1][16];   // 32KB: W1[k][fh + 4*f4 .. +3]
    __shared__ float  xs[32][F1];    // 16KB
    int tid = threadIdx.x;
    int fh = blockIdx.y * 64;
    for (int idx = tid; idx < F1 * 16; idx += 256) {
        int k = idx >> 4, f4 = idx & 15;
        W4s[k][f4] = *(const float4*)(W1 + k * F1 + fh + 4 * f4);
    }
    int nd = tid >> 4;      // 0..15
    int f4 = tid & 15;      // 0..15 -> features fh+4*f4..+3
    int fo = (fh >> 2) + f4;
    int ntiles = (N + 31) >> 5;
    for (int t = blockIdx.x; t < ntiles; t += gridDim.x) {
        int base = t << 5;
        __syncthreads();   // xs reuse (also covers initial W load)
        for (int idx = tid; idx < 32 * (F1 / 4); idx += 256) {
            int r = idx >> 5, c4 = idx & 31;
            int nn = base + r;
            float4 v = (nn < N) ? *(const float4*)(x + (size_t)nn * F1 + 4 * c4)
                                : make_float4(0.f, 0.f, 0.f, 0.f);
            *(float4*)&xs[r][4 * c4] = v;
        }
        __syncthreads();
        unsigned long long a0lo = 0ull, a0hi = 0ull, a1lo = 0ull, a1hi = 0ull;
        #pragma unroll 4
        for (int k = 0; k < F1; k++) {
            ulonglong2 w = *(const ulonglong2*)&W4s[k][f4];   // (w.x,w.y),(w.z,w.w)
            unsigned long long xa = bcast2(xs[nd][k]);
            unsigned long long xb = bcast2(xs[nd + 16][k]);
            ffma2(a0lo, xa, w.x); ffma2(a0hi, xa, w.y);
            ffma2(a1lo, xb, w.x); ffma2(a1hi, xb, w.y);
        }
        int na = base + nd, nb = base + nd + 16;
        if (na < N) {
            float d = g_dinv[na];
            float2 lo = unpack2(a0lo), hi = unpack2(a0hi);
            g_h1s[(size_t)na * (F1 / 4) + fo] =
                make_float4(lo.x * d, lo.y * d, hi.x * d, hi.y * d);
        }
        if (nb < N) {
            float d = g_dinv[nb];
            float2 lo = unpack2(a1lo), hi = unpack2(a1hi);
            g_h1s[(size_t)nb * (F1 / 4) + fo] =
                make_float4(lo.x * d, lo.y * d, hi.x * d, hi.y * d);
        }
    }
}

// Aggregate layer 1: warp per node, 8-way unrolled gather, fused relu+bias.
__global__ void __launch_bounds__(256) k_agg1(const float* __restrict__ b1, int N) {
    int lane  = threadIdx.x & 31;
    int warp  = (blockIdx.x * blockDim.x + threadIdx.x) >> 5;
    int nwarp = (gridDim.x * blockDim.x) >> 5;
    float bx = b1[4 * lane + 0], by = b1[4 * lane + 1];
    float bz = b1[4 * lane + 2], bw = b1[4 * lane + 3];
    for (int n = warp; n < N; n += nwarp) {
        float4 acc = g_h1s[(size_t)n * (F1 / 4) + lane];   // self loop
        int s = g_rowstart[n], e = g_rowstart[n + 1];
        int i = s;
        for (; i + 8 <= e; i += 8) {
            int i0 = g_csr[i],     i1 = g_csr[i + 1], i2 = g_csr[i + 2], i3 = g_csr[i + 3];
            int i4 = g_csr[i + 4], i5 = g_csr[i + 5], i6 = g_csr[i + 6], i7 = g_csr[i + 7];
            float4 v0 = g_h1s[(size_t)i0 * (F1 / 4) + lane];
            float4 v1 = g_h1s[(size_t)i1 * (F1 / 4) + lane];
            float4 v2 = g_h1s[(size_t)i2 * (F1 / 4) + lane];
            float4 v3 = g_h1s[(size_t)i3 * (F1 / 4) + lane];
            float4 v4 = g_h1s[(size_t)i4 * (F1 / 4) + lane];
            float4 v5 = g_h1s[(size_t)i5 * (F1 / 4) + lane];
            float4 v6 = g_h1s[(size_t)i6 * (F1 / 4) + lane];
            float4 v7 = g_h1s[(size_t)i7 * (F1 / 4) + lane];
            acc.x += (v0.x + v1.x) + (v2.x + v3.x) + (v4.x + v5.x) + (v6.x + v7.x);
            acc.y += (v0.y + v1.y) + (v2.y + v3.y) + (v4.y + v5.y) + (v6.y + v7.y);
            acc.z += (v0.z + v1.z) + (v2.z + v3.z) + (v4.z + v5.z) + (v6.z + v7.z);
            acc.w += (v0.w + v1.w) + (v2.w + v3.w) + (v4.w + v5.w) + (v6.w + v7.w);
        }
        for (; i + 4 <= e; i += 4) {
            int i0 = g_csr[i], i1 = g_csr[i + 1], i2 = g_csr[i + 2], i3 = g_csr[i + 3];
            float4 v0 = g_h1s[(size_t)i0 * (F1 / 4) + lane];
            float4 v1 = g_h1s[(size_t)i1 * (F1 / 4) + lane];
            float4 v2 = g_h1s[(size_t)i2 * (F1 / 4) + lane];
            float4 v3 = g_h1s[(size_t)i3 * (F1 / 4) + lane];
            acc.x += (v0.x + v1.x) + (v2.x + v3.x);
            acc.y += (v0.y + v1.y) + (v2.y + v3.y);
            acc.z += (v0.z + v1.z) + (v2.z + v3.z);
            acc.w += (v0.w + v1.w) + (v2.w + v3.w);
        }
        for (; i < e; i++) {
            int src = g_csr[i];
            float4 v = g_h1s[(size_t)src * (F1 / 4) + lane];
            acc.x += v.x; acc.y += v.y; acc.z += v.z; acc.w += v.w;
        }
        float dn = g_dinv[n];
        float4 o;
        o.x = fmaxf(fmaf(dn, acc.x, bx), 0.f);
        o.y = fmaxf(fmaf(dn, acc.y, by), 0.f);
        o.z = fmaxf(fmaf(dn, acc.z, bz), 0.f);
        o.w = fmaxf(fmaf(dn, acc.w, bw), 0.f);
        g_hidden[(size_t)n * (F1 / 4) + lane] = o;
    }
}

// Register-tiled GEMM2 with packed f32x2 FMA. Tile: 32 nodes x 64 features.
__global__ void __launch_bounds__(256) k_gemm2(const float* __restrict__ W2, int N) {
    __shared__ float4 W4s[F1][16];   // 32KB: W2[k][4*f4 .. +3]
    __shared__ float  xs[32][F1];    // 16KB
    int tid = threadIdx.x;
    for (int idx = tid; idx < F1 * 16; idx += 256) {
        int k = idx >> 4, f4 = idx & 15;
        W4s[k][f4] = *(const float4*)(W2 + k * F2 + 4 * f4);
    }
    int nd = tid >> 4;
    int f4 = tid & 15;
    const float* hidden = (const float*)g_hidden;
    int ntiles = (N + 31) >> 5;
    for (int t = blockIdx.x; t < ntiles; t += gridDim.x) {
        int base = t << 5;
        __syncthreads();
        for (int idx = tid; idx < 32 * (F1 / 4); idx += 256) {
            int r = idx >> 5, c4 = idx & 31;
            int nn = base + r;
            float4 v = (nn < N) ? *(const float4*)(hidden + (size_t)nn * F1 + 4 * c4)
                                : make_float4(0.f, 0.f, 0.f, 0.f);
            *(float4*)&xs[r][4 * c4] = v;
        }
        __syncthreads();
        unsigned long long a0lo = 0ull, a0hi = 0ull, a1lo = 0ull, a1hi = 0ull;
        #pragma unroll 4
        for (int k = 0; k < F1; k++) {
            ulonglong2 w = *(const ulonglong2*)&W4s[k][f4];
            unsigned long long xa = bcast2(xs[nd][k]);
            unsigned long long xb = bcast2(xs[nd + 16][k]);
            ffma2(a0lo, xa, w.x); ffma2(a0hi, xa, w.y);
            ffma2(a1lo, xb, w.x); ffma2(a1hi, xb, w.y);
        }
        int na = base + nd, nb = base + nd + 16;
        if (na < N) {
            float d = g_dinv[na];
            float2 lo = unpack2(a0lo), hi = unpack2(a0hi);
            g_h2s[(size_t)na * (F2 / 4) + f4] =
                make_float4(lo.x * d, lo.y * d, hi.x * d, hi.y * d);
        }
        if (nb < N) {
            float d = g_dinv[nb];
            float2 lo = unpack2(a1lo), hi = unpack2(a1hi);
            g_h2s[(size_t)nb * (F2 / 4) + f4] =
                make_float4(lo.x * d, lo.y * d, hi.x * d, hi.y * d);
        }
    }
}

// Aggregate layer 2: warp per node, 8-way unrolled gather, fused bias.
__global__ void __launch_bounds__(256) k_agg2(const float* __restrict__ b2,
                                              float* __restrict__ out, int N) {
    int lane  = threadIdx.x & 31;
    int warp  = (blockIdx.x * blockDim.x + threadIdx.x) >> 5;
    int nwarp = (gridDim.x * blockDim.x) >> 5;
    float bx = b2[2 * lane + 0], by = b2[2 * lane + 1];
    const float2* h2s = (const float2*)g_h2s;
    for (int n = warp; n < N; n += nwarp) {
        float2 acc = h2s[(size_t)n * (F2 / 2) + lane];   // self loop
        int s = g_rowstart[n], e = g_rowstart[n + 1];
        int i = s;
        for (; i + 8 <= e; i += 8) {
            int i0 = g_csr[i],     i1 = g_csr[i + 1], i2 = g_csr[i + 2], i3 = g_csr[i + 3];
            int i4 = g_csr[i + 4], i5 = g_csr[i + 5], i6 = g_csr[i + 6], i7 = g_csr[i + 7];
            float2 v0 = h2s[(size_t)i0 * (F2 / 2) + lane];
            float2 v1 = h2s[(size_t)i1 * (F2 / 2) + lane];
            float2 v2 = h2s[(size_t)i2 * (F2 / 2) + lane];
            float2 v3 = h2s[(size_t)i3 * (F2 / 2) + lane];
            float2 v4 = h2s[(size_t)i4 * (F2 / 2) + lane];
            float2 v5 = h2s[(size_t)i5 * (F2 / 2) + lane];
            float2 v6 = h2s[(size_t)i6 * (F2 / 2) + lane];
            float2 v7 = h2s[(size_t)i7 * (F2 / 2) + lane];
            acc.x += (v0.x + v1.x) + (v2.x + v3.x) + (v4.x + v5.x) + (v6.x + v7.x);
            acc.y += (v0.y + v1.y) + (v2.y + v3.y) + (v4.y + v5.y) + (v6.y + v7.y);
        }
        for (; i + 4 <= e; i += 4) {
            int i0 = g_csr[i], i1 = g_csr[i + 1], i2 = g_csr[i + 2], i3 = g_csr[i + 3];
            float2 v0 = h2s[(size_t)i0 * (F2 / 2) + lane];
            float2 v1 = h2s[(size_t)i1 * (F2 / 2) + lane];
            float2 v2 = h2s[(size_t)i2 * (F2 / 2) + lane];
            float2 v3 = h2s[(size_t)i3 * (F2 / 2) + lane];
            acc.x += (v0.x + v1.x) + (v2.x + v3.x);
            acc.y += (v0.y + v1.y) + (v2.y + v3.y);
        }
        for (; i < e; i++) {
            int src = g_csr[i];
            float2 v = h2s[(size_t)src * (F2 / 2) + lane];
            acc.x += v.x; acc.y += v.y;
        }
        float dn = g_dinv[n];
        out[(size_t)n * F2 + 2 * lane + 0] = fmaf(dn, acc.x, bx);
        out[(size_t)n * F2 + 2 * lane + 1] = fmaf(dn, acc.y, by);
    }
}

// ---------------- launcher ---------------------------------------------------

extern "C" void kernel_launch(void* const* d_in, const int* in_sizes, int n_in,
                              void* d_out, int out_size) {
    const float* x  = (const float*)d_in[0];
    const void*  ei = d_in[1];                 // int32 or int64 — probed on device
    // d_in[2] = edge_weight (unused: reference overwrites with ones)
    const float* W1 = (const float*)d_in[3];
    const float* b1 = (const float*)d_in[4];
    const float* W2 = (const float*)d_in[5];
    const float* b2 = (const float*)d_in[6];
    float*       out = (float*)d_out;

    int N = in_sizes[0] / F1;
    int E = in_sizes[1] / 2;
    if (N > NMAX) N = NMAX;
    if (E > EMAX) E = EMAX;
    int nb = (N + SCAN_B - 1) / SCAN_B;

    k_detect<<<1, 32>>>((const int*)ei);
    k_zero_cnt<<<(N + 255) / 256, 256>>>(N);
    k_count<<<(E + 255) / 256, 256>>>(ei, E, N);
    k_scan_partial<<<nb, SCAN_B>>>(N);
    k_scan_blk<<<1, 256>>>(nb, N);
    k_scan_apply<<<nb, SCAN_B>>>(N);
    k_fill<<<(E + 255) / 256, 256>>>(E);

    dim3 g1(592, 2);
    k_gemm1<<<g1, 256>>>(x, W1, N);
    k_agg1<<<(N + 7) / 8, 256>>>(b1, N);
    k_gemm2<<<592, 256>>>(W2, N);
    k_agg2<<<(N + 7) / 8, 256>>>(b2, out, N);
}

// round 10
// speedup vs baseline: 1.0733x; 1.0733x over previous
#include <cuda_runtime.h>
#include <cuda_bf16.h>
#include <math.h>

// Problem constants (shapes fixed by the dataset)
#define NMAX  100000
#define EMAX  1600000
#define F1    128
#define F2    64
#define SCAN_B 512
#define NBMAX ((NMAX + SCAN_B - 1) / SCAN_B)   // 196

// ---------------- scratch (static device globals; no allocation allowed) ----
__device__ int    g_is64;                 // 1 if edge_index is int64, else int32
__device__ int    g_cnt[NMAX];
__device__ int    g_bsum[NBMAX];
__device__ int    g_boff[NBMAX];
__device__ int    g_rowstart[NMAX + 1];
__device__ int    g_cursor[NMAX];
__device__ float  g_dinv[NMAX];
__device__ int    g_csr[EMAX];
__device__ float4 g_h1s[(size_t)NMAX * F1 / 4];     // (x @ W1) * dinv[row]
__device__ float4 g_hidden[(size_t)NMAX * F1 / 4];  // relu(dinv*(sum)+b1)
__device__ float4 g_h2s[(size_t)NMAX * F2 / 4];     // (hidden @ W2) * dinv[row]

// ---------------- build kernels ---------------------------------------------

// Probe dtype of edge_index: int64 values < 2^31 have zero high words.
__global__ void k_detect(const int* __restrict__ ei_raw) {
    if (threadIdx.x == 0 && blockIdx.x == 0) {
        int any = 0;
        for (int i = 0; i < 64; i++) any |= ei_raw[2 * i + 1];
        g_is64 = (any == 0) ? 1 : 0;
    }
}

__global__ void k_zero_cnt(int N) {
    int i = blockIdx.x * blockDim.x + threadIdx.x;
    if (i < N) g_cnt[i] = 0;
}

// Decode edge target (int32 or int64 per flag), validate, count in-degree.
__global__ void k_count(const void* __restrict__ ei_raw, int E, int N) {
    int e = blockIdx.x * blockDim.x + threadIdx.x;
    if (e >= E) return;
    int c;
    if (g_is64) {
        const long long* ei = (const long long*)ei_raw;
        c = (int)ei[(size_t)E + e];
    } else {
        const int* ei = (const int*)ei_raw;
        c = ei[(size_t)E + e];
    }
    if ((unsigned)c < (unsigned)N) atomicAdd(&g_cnt[c], 1);
}

// dinv depends only on counts — computed early so GEMM1 can fork off here.
__global__ void k_dinv(int N) {
    int i = blockIdx.x * blockDim.x + threadIdx.x;
    if (i < N) g_dinv[i] = rsqrtf((float)(g_cnt[i] + 1));   // +1 self loop
}

// Phase 1: per-block sums of counts.
__global__ void __launch_bounds__(SCAN_B) k_scan_partial(int N) {
    __shared__ int red[SCAN_B / 32];
    int b = blockIdx.x, tid = threadIdx.x;
    int i = b * SCAN_B + tid;
    int v = (i < N) ? g_cnt[i] : 0;
    for (int o = 16; o > 0; o >>= 1) v += __shfl_down_sync(0xffffffffu, v, o);
    if ((tid & 31) == 0) red[tid >> 5] = v;
    __syncthreads();
    if (tid < SCAN_B / 32) {
        int s = red[tid];
        for (int o = (SCAN_B / 64); o > 0; o >>= 1) s += __shfl_down_sync(0xffffu, s, o);
        if (tid == 0) g_bsum[b] = s;
    }
}

// Phase 2: single block scans block sums -> exclusive offsets; writes total.
__global__ void __launch_bounds__(256) k_scan_blk(int nb, int N) {
    __shared__ int sh[256];
    int tid = threadIdx.x;
    int v = (tid < nb) ? g_bsum[tid] : 0;
    sh[tid] = v;
    __syncthreads();
    for (int o = 1; o < 256; o <<= 1) {
        int t = (tid >= o) ? sh[tid - o] : 0;
        __syncthreads();
        sh[tid] += t;
        __syncthreads();
    }
    if (tid < nb) g_boff[tid] = sh[tid] - v;       // exclusive
    if (tid == 255) g_rowstart[N] = sh[255];       // total
}

// Phase 3: block-local exclusive scan + offset -> rowstart/cursor.
__global__ void __launch_bounds__(SCAN_B) k_scan_apply(int N) {
    __shared__ int sh[SCAN_B];
    int b = blockIdx.x, tid = threadIdx.x;
    int i = b * SCAN_B + tid;
    int v = (i < N) ? g_cnt[i] : 0;
    sh[tid] = v;
    __syncthreads();
    for (int o = 1; o < SCAN_B; o <<= 1) {
        int t = (tid >= o) ? sh[tid - o] : 0;
        __syncthreads();
        sh[tid] += t;
        __syncthreads();
    }
    if (i < N) {
        int base = g_boff[b] + sh[tid] - v;        // exclusive prefix
        g_rowstart[i] = base;
        g_cursor[i]   = base;
    }
}

// Fill CSR: decode edges directly (no staging), place source into target bucket.
__global__ void k_fill(const void* __restrict__ ei_raw, int E, int N) {
    int e = blockIdx.x * blockDim.x + threadIdx.x;
    if (e >= E) return;
    int r, c;
    if (g_is64) {
        const long long* ei = (const long long*)ei_raw;
        r = (int)ei[e];
        c = (int)ei[(size_t)E + e];
    } else {
        const int* ei = (const int*)ei_raw;
        r = ei[e];
        c = ei[(size_t)E + e];
    }
    if ((unsigned)r >= (unsigned)N || (unsigned)c >= (unsigned)N) return;
    int pos = atomicAdd(&g_cursor[c], 1);
    g_csr[pos] = r;
}

// ---------------- compute kernels -------------------------------------------

// Register-tiled GEMM1: h1s[n, fh+4*f4..+3] = (x[n] @ W1[:, ...]) * dinv[n].
// Block tile: 32 nodes x 64 features (half of F1, chosen by blockIdx.y).
// 256 threads, each computes 2 nodes x float4 features (8 outputs).
__global__ void __launch_bounds__(256) k_gemm1(const float* __restrict__ x,
                                               const float* __restrict__ W1, int N) {
    __shared__ float4 W4s[F1][16];   // 32KB: W1[k][fh + 4*f4 .. +3]
    __shared__ float  xs[32][F1];    // 16KB
    int tid = threadIdx.x;
    int fh = blockIdx.y * 64;
    for (int idx = tid; idx < F1 * 16; idx += 256) {
        int k = idx >> 4, f4 = idx & 15;
        W4s[k][f4] = *(const float4*)(W1 + k * F1 + fh + 4 * f4);
    }
    int nd = tid >> 4;      // 0..15
    int f4 = tid & 15;      // 0..15 -> features fh+4*f4..+3
    int fo = (fh >> 2) + f4;
    int ntiles = (N + 31) >> 5;
    for (int t = blockIdx.x; t < ntiles; t += gridDim.x) {
        int base = t << 5;
        __syncthreads();   // xs reuse (also covers initial W load)
        for (int idx = tid; idx < 32 * (F1 / 4); idx += 256) {
            int r = idx >> 5, c4 = idx & 31;
            int nn = base + r;
            float4 v = (nn < N) ? *(const float4*)(x + (size_t)nn * F1 + 4 * c4)
                                : make_float4(0.f, 0.f, 0.f, 0.f);
            *(float4*)&xs[r][4 * c4] = v;
        }
        __syncthreads();
        float4 a0 = make_float4(0.f, 0.f, 0.f, 0.f);
        float4 a1 = make_float4(0.f, 0.f, 0.f, 0.f);
        #pragma unroll 4
        for (int k = 0; k < F1; k++) {
            float4 w = W4s[k][f4];
            float xa = xs[nd][k];
            float xb = xs[nd + 16][k];
            a0.x = fmaf(xa, w.x, a0.x); a0.y = fmaf(xa, w.y, a0.y);
            a0.z = fmaf(xa, w.z, a0.z); a0.w = fmaf(xa, w.w, a0.w);
            a1.x = fmaf(xb, w.x, a1.x); a1.y = fmaf(xb, w.y, a1.y);
            a1.z = fmaf(xb, w.z, a1.z); a1.w = fmaf(xb, w.w, a1.w);
        }
        int na = base + nd, nb = base + nd + 16;
        if (na < N) {
            float d = g_dinv[na];
            g_h1s[(size_t)na * (F1 / 4) + fo] =
                make_float4(a0.x * d, a0.y * d, a0.z * d, a0.w * d);
        }
        if (nb < N) {
            float d = g_dinv[nb];
            g_h1s[(size_t)nb * (F1 / 4) + fo] =
                make_float4(a1.x * d, a1.y * d, a1.z * d, a1.w * d);
        }
    }
}

// Aggregate layer 1: warp per node, 4-way unrolled gather, fused relu+bias.
__global__ void __launch_bounds__(256) k_agg1(const float* __restrict__ b1, int N) {
    int lane  = threadIdx.x & 31;
    int warp  = (blockIdx.x * blockDim.x + threadIdx.x) >> 5;
    int nwarp = (gridDim.x * blockDim.x) >> 5;
    float bx = b1[4 * lane + 0], by = b1[4 * lane + 1];
    float bz = b1[4 * lane + 2], bw = b1[4 * lane + 3];
    for (int n = warp; n < N; n += nwarp) {
        float4 acc = g_h1s[(size_t)n * (F1 / 4) + lane];   // self loop
        int s = g_rowstart[n], e = g_rowstart[n + 1];
        int i = s;
        for (; i + 4 <= e; i += 4) {
            int s0 = g_csr[i], s1 = g_csr[i + 1], s2 = g_csr[i + 2], s3 = g_csr[i + 3];
            float4 v0 = g_h1s[(size_t)s0 * (F1 / 4) + lane];
            float4 v1 = g_h1s[(size_t)s1 * (F1 / 4) + lane];
            float4 v2 = g_h1s[(size_t)s2 * (F1 / 4) + lane];
            float4 v3 = g_h1s[(size_t)s3 * (F1 / 4) + lane];
            acc.x += (v0.x + v1.x) + (v2.x + v3.x);
            acc.y += (v0.y + v1.y) + (v2.y + v3.y);
            acc.z += (v0.z + v1.z) + (v2.z + v3.z);
            acc.w += (v0.w + v1.w) + (v2.w + v3.w);
        }
        for (; i < e; i++) {
            int src = g_csr[i];
            float4 v = g_h1s[(size_t)src * (F1 / 4) + lane];
            acc.x += v.x; acc.y += v.y; acc.z += v.z; acc.w += v.w;
        }
        float dn = g_dinv[n];
        float4 o;
        o.x = fmaxf(fmaf(dn, acc.x, bx), 0.f);
        o.y = fmaxf(fmaf(dn, acc.y, by), 0.f);
        o.z = fmaxf(fmaf(dn, acc.z, bz), 0.f);
        o.w = fmaxf(fmaf(dn, acc.w, bw), 0.f);
        g_hidden[(size_t)n * (F1 / 4) + lane] = o;
    }
}

// Register-tiled GEMM2: h2s[n] = (hidden[n] @ W2) * dinv[n].
__global__ void __launch_bounds__(256) k_gemm2(const float* __restrict__ W2, int N) {
    __shared__ float4 W4s[F1][16];   // 32KB: W2[k][4*f4 .. +3]
    __shared__ float  xs[32][F1];    // 16KB
    int tid = threadIdx.x;
    for (int idx = tid; idx < F1 * 16; idx += 256) {
        int k = idx >> 4, f4 = idx & 15;
        W4s[k][f4] = *(const float4*)(W2 + k * F2 + 4 * f4);
    }
    int nd = tid >> 4;
    int f4 = tid & 15;
    const float* hidden = (const float*)g_hidden;
    int ntiles = (N + 31) >> 5;
    for (int t = blockIdx.x; t < ntiles; t += gridDim.x) {
        int base = t << 5;
        __syncthreads();
        for (int idx = tid; idx < 32 * (F1 / 4); idx += 256) {
            int r = idx >> 5, c4 = idx & 31;
            int nn = base + r;
            float4 v = (nn < N) ? *(const float4*)(hidden + (size_t)nn * F1 + 4 * c4)
                                : make_float4(0.f, 0.f, 0.f, 0.f);
            *(float4*)&xs[r][4 * c4] = v;
        }
        __syncthreads();
        float4 a0 = make_float4(0.f, 0.f, 0.f, 0.f);
        float4 a1 = make_float4(0.f, 0.f, 0.f, 0.f);
        #pragma unroll 4
        for (int k = 0; k < F1; k++) {
            float4 w = W4s[k][f4];
            float xa = xs[nd][k];
            float xb = xs[nd + 16][k];
            a0.x = fmaf(xa, w.x, a0.x); a0.y = fmaf(xa, w.y, a0.y);
            a0.z = fmaf(xa, w.z, a0.z); a0.w = fmaf(xa, w.w, a0.w);
            a1.x = fmaf(xb, w.x, a1.x); a1.y = fmaf(xb, w.y, a1.y);
            a1.z = fmaf(xb, w.z, a1.z); a1.w = fmaf(xb, w.w, a1.w);
        }
        int na = base + nd, nb = base + nd + 16;
        if (na < N) {
            float d = g_dinv[na];
            g_h2s[(size_t)na * (F2 / 4) + f4] =
                make_float4(a0.x * d, a0.y * d, a0.z * d, a0.w * d);
        }
        if (nb < N) {
            float d = g_dinv[nb];
            g_h2s[(size_t)nb * (F2 / 4) + f4] =
                make_float4(a1.x * d, a1.y * d, a1.z * d, a1.w * d);
        }
    }
}

// Aggregate layer 2: warp per node, 4-way unrolled gather, fused bias.
__global__ void __launch_bounds__(256) k_agg2(const float* __restrict__ b2,
                                              float* __restrict__ out, int N) {
    int lane  = threadIdx.x & 31;
    int warp  = (blockIdx.x * blockDim.x + threadIdx.x) >> 5;
    int nwarp = (gridDim.x * blockDim.x) >> 5;
    float bx = b2[2 * lane + 0], by = b2[2 * lane + 1];
    const float2* h2s = (const float2*)g_h2s;
    for (int n = warp; n < N; n += nwarp) {
        float2 acc = h2s[(size_t)n * (F2 / 2) + lane];   // self loop
        int s = g_rowstart[n], e = g_rowstart[n + 1];
        int i = s;
        for (; i + 4 <= e; i += 4) {
            int s0 = g_csr[i], s1 = g_csr[i + 1], s2 = g_csr[i + 2], s3 = g_csr[i + 3];
            float2 v0 = h2s[(size_t)s0 * (F2 / 2) + lane];
            float2 v1 = h2s[(size_t)s1 * (F2 / 2) + lane];
            float2 v2 = h2s[(size_t)s2 * (F2 / 2) + lane];
            float2 v3 = h2s[(size_t)s3 * (F2 / 2) + lane];
            acc.x += (v0.x + v1.x) + (v2.x + v3.x);
            acc.y += (v0.y + v1.y) + (v2.y + v3.y);
        }
        for (; i < e; i++) {
            int src = g_csr[i];
            float2 v = h2s[(size_t)src * (F2 / 2) + lane];
            acc.x += v.x; acc.y += v.y;
        }
        float dn = g_dinv[n];
        out[(size_t)n * F2 + 2 * lane + 0] = fmaf(dn, acc.x, bx);
        out[(size_t)n * F2 + 2 * lane + 1] = fmaf(dn, acc.y, by);
    }
}

// ---------------- launcher ---------------------------------------------------

static cudaStream_t aux_stream() {
    static cudaStream_t s = nullptr;
    if (!s) cudaStreamCreateWithFlags(&s, cudaStreamNonBlocking);
    return s;
}
static cudaEvent_t aux_event(int which) {
    static cudaEvent_t ev[2] = {nullptr, nullptr};
    if (!ev[which]) cudaEventCreateWithFlags(&ev[which], cudaEventDisableTiming);
    return ev[which];
}

extern "C" void kernel_launch(void* const* d_in, const int* in_sizes, int n_in,
                              void* d_out, int out_size) {
    const float* x  = (const float*)d_in[0];
    const void*  ei = d_in[1];                 // int32 or int64 — probed on device
    // d_in[2] = edge_weight (unused: reference overwrites with ones)
    const float* W1 = (const float*)d_in[3];
    const float* b1 = (const float*)d_in[4];
    const float* W2 = (const float*)d_in[5];
    const float* b2 = (const float*)d_in[6];
    float*       out = (float*)d_out;

    int N = in_sizes[0] / F1;
    int E = in_sizes[1] / 2;
    if (N > NMAX) N = NMAX;
    if (E > EMAX) E = EMAX;
    int nb = (N + SCAN_B - 1) / SCAN_B;

    cudaStream_t s2 = aux_stream();
    cudaEvent_t evFork = aux_event(0);
    cudaEvent_t evJoin = aux_event(1);

    // --- serial prefix: dtype probe, degree counts, dinv ---
    k_detect<<<1, 32>>>((const int*)ei);
    k_zero_cnt<<<(N + 255) / 256, 256>>>(N);
    k_count<<<(E + 255) / 256, 256>>>(ei, E, N);
    k_dinv<<<(N + 255) / 256, 256>>>(N);

    // --- fork: GEMM1 (needs only dinv) runs concurrent with CSR build ---
    cudaEventRecord(evFork, 0);
    cudaStreamWaitEvent(s2, evFork, 0);
    dim3 g1(592, 2);
    k_gemm1<<<g1, 256, 0, s2>>>(x, W1, N);
    cudaEventRecord(evJoin, s2);

    k_scan_partial<<<nb, SCAN_B>>>(N);
    k_scan_blk<<<1, 256>>>(nb, N);
    k_scan_apply<<<nb, SCAN_B>>>(N);
    k_fill<<<(E + 255) / 256, 256>>>(ei, E, N);

    // --- join: aggregation needs both CSR and h1s ---
    cudaStreamWaitEvent(0, evJoin, 0);
    k_agg1<<<(N + 7) / 8, 256>>>(b1, N);
    k_gemm2<<<592, 256>>>(W2, N);
    k_agg2<<<(N + 7) / 8, 256>>>(b2, out, N);
}